// round 15
// baseline (speedup 1.0000x reference)
#include <cuda_runtime.h>
#include <cuda_fp16.h>
#include <cstdint>

#define NB      40
#define C       128
#define BATCH   4
#define TMAX    8192
#define SKIP_T  4096
#define TN      64

// ======================= device scratch (no allocs allowed) =======================
__device__ float g_x0[BATCH * TMAX * C];
__device__ float g_x1[BATCH * TMAX * C];
// A-operand fragments (fp16), packed per-lane in mma register order. Each slot = 2 x uint4 (hi, lo).
__device__ uint4 g_wAf[NB * 16 * 8 * 32 * 2];   // GEMM1: 16 ksteps (hi+lo used)
__device__ uint4 g_wRf[NB *  8 * 8 * 32 * 2];   // res:   8 ksteps (hi used)
__device__ uint4 g_wSf[NB *  8 * 8 * 32 * 2];   // skip:  8 ksteps (hi used)

#define SWZ(o) ((uint32_t)(o) ^ ((((uint32_t)(o)) >> 3) & 0x70u))

__device__ __forceinline__ uint32_t smem_to_u32(const void* p) {
    uint32_t a;
    asm("{ .reg .u64 t; cvta.to.shared.u64 t, %1; cvt.u32.u64 %0, t; }" : "=r"(a) : "l"(p));
    return a;
}

__device__ __forceinline__ void mma_f16(float* c, const uint32_t* a, const uint32_t* b) {
    asm volatile("mma.sync.aligned.m16n8k16.row.col.f32.f16.f16.f32 "
        "{%0,%1,%2,%3}, {%4,%5,%6,%7}, {%8,%9}, {%0,%1,%2,%3};"
        : "+f"(c[0]), "+f"(c[1]), "+f"(c[2]), "+f"(c[3])
        : "r"(a[0]), "r"(a[1]), "r"(a[2]), "r"(a[3]), "r"(b[0]), "r"(b[1]));
}

__device__ __forceinline__ void ldsm_x4(uint32_t* r, uint32_t addr) {
    asm volatile("ldmatrix.sync.aligned.m8n8.x4.shared.b16 {%0,%1,%2,%3}, [%4];"
        : "=r"(r[0]), "=r"(r[1]), "=r"(r[2]), "=r"(r[3]) : "r"(addr));
}
__device__ __forceinline__ void ldsm_x4_t(uint32_t* r, uint32_t addr) {
    asm volatile("ldmatrix.sync.aligned.m8n8.x4.trans.shared.b16 {%0,%1,%2,%3}, [%4];"
        : "=r"(r[0]), "=r"(r[1]), "=r"(r[2]), "=r"(r[3]) : "r"(addr));
}

__device__ __forceinline__ uint32_t pk2h(float a, float b) {
    __half2 t = __floats2half2_rn(a, b);
    return *reinterpret_cast<uint32_t*>(&t);
}
__device__ __forceinline__ void hilo_h(float v, float& h, float& l) {
    h = __half2float(__float2half_rn(v));
    l = v - h;
}

// gate(y) = tanh(y)*sigmoid(y) = (1-u)/(1+u^2), u = e^{-y}  (exact identity)
__device__ __forceinline__ float gatef(float y) {
    float u = __expf(-fmaxf(y, -15.f));
    return __fdividef(1.f - u, 1.f + u * u);
}

// ======================= transpose input [b][c][t] -> scratch [b][t][c] =======================
__global__ void transpose_in(const float* __restrict__ x, float* __restrict__ xt) {
    __shared__ float tile[32][33];
    const int b  = blockIdx.z;
    const int c0 = blockIdx.y * 32;
    const int tb = blockIdx.x * 32;
    const int tx = threadIdx.x, ty = threadIdx.y;
    #pragma unroll
    for (int i = 0; i < 32; i += 8)
        tile[ty + i][tx] = x[((size_t)b * C + c0 + ty + i) * TMAX + tb + tx];
    __syncthreads();
    #pragma unroll
    for (int i = 0; i < 32; i += 8)
        xt[((size_t)b * TMAX + tb + ty + i) * C + c0 + tx] = tile[tx][ty + i];
}

// ======================= prep: pack fp16 A fragments in register order =======================
__global__ void prep_frags(const float* __restrict__ w_dil,
                           const float* __restrict__ w_res,
                           const float* __restrict__ w_skip) {
    int idx = blockIdx.x * blockDim.x + threadIdx.x;
    if (idx < NB * 16 * 8 * 32) {
        int lane = idx & 31, mt = (idx >> 5) & 7, ks = (idx >> 8) & 15, blk = idx >> 12;
        int r = lane >> 2, c2 = (lane & 3) * 2;
        int mr[2] = { mt * 16 + r, mt * 16 + r + 8 };
        int kc[2] = { ks * 16 + c2, ks * 16 + c2 + 8 };
        float h[2][2][2], l[2][2][2];
        #pragma unroll
        for (int mi = 0; mi < 2; mi++)
            #pragma unroll
            for (int kh = 0; kh < 2; kh++)
                #pragma unroll
                for (int e = 0; e < 2; e++) {
                    int k = kc[kh] + e;
                    int tap = k >> 7, ch = k & 127;
                    float v = w_dil[(((size_t)blk * C + mr[mi]) * C + ch) * 2 + tap];
                    hilo_h(v, h[mi][kh][e], l[mi][kh][e]);
                }
        uint4 hv = { pk2h(h[0][0][0], h[0][0][1]), pk2h(h[1][0][0], h[1][0][1]),
                     pk2h(h[0][1][0], h[0][1][1]), pk2h(h[1][1][0], h[1][1][1]) };
        uint4 lv = { pk2h(l[0][0][0], l[0][0][1]), pk2h(l[1][0][0], l[1][0][1]),
                     pk2h(l[0][1][0], l[0][1][1]), pk2h(l[1][1][0], l[1][1][1]) };
        g_wAf[(size_t)idx * 2]     = hv;
        g_wAf[(size_t)idx * 2 + 1] = lv;
    }
    if (idx < NB * 8 * 8 * 32) {
        int lane = idx & 31, mt = (idx >> 5) & 7, ks = (idx >> 8) & 7, blk = idx >> 11;
        int r = lane >> 2, c2 = (lane & 3) * 2;
        int mr[2] = { mt * 16 + r, mt * 16 + r + 8 };
        int kc[2] = { ks * 16 + c2, ks * 16 + c2 + 8 };
        float hR[2][2][2], lR[2][2][2], hS[2][2][2], lS[2][2][2];
        #pragma unroll
        for (int mi = 0; mi < 2; mi++)
            #pragma unroll
            for (int kh = 0; kh < 2; kh++)
                #pragma unroll
                for (int e = 0; e < 2; e++) {
                    int k = kc[kh] + e;
                    float vr = w_res [((size_t)blk * C + mr[mi]) * C + k];
                    float vs = w_skip[((size_t)blk * C + mr[mi]) * C + k];
                    hilo_h(vr, hR[mi][kh][e], lR[mi][kh][e]);
                    hilo_h(vs, hS[mi][kh][e], lS[mi][kh][e]);
                }
        uint4 v;
        v = make_uint4(pk2h(hR[0][0][0],hR[0][0][1]), pk2h(hR[1][0][0],hR[1][0][1]),
                       pk2h(hR[0][1][0],hR[0][1][1]), pk2h(hR[1][1][0],hR[1][1][1]));
        g_wRf[(size_t)idx * 2] = v;
        v = make_uint4(pk2h(lR[0][0][0],lR[0][0][1]), pk2h(lR[1][0][0],lR[1][0][1]),
                       pk2h(lR[0][1][0],lR[0][1][1]), pk2h(lR[1][1][0],lR[1][1][1]));
        g_wRf[(size_t)idx * 2 + 1] = v;
        v = make_uint4(pk2h(hS[0][0][0],hS[0][0][1]), pk2h(hS[1][0][0],hS[1][0][1]),
                       pk2h(hS[0][1][0],hS[0][1][1]), pk2h(hS[1][1][0],hS[1][1][1]));
        g_wSf[(size_t)idx * 2] = v;
        v = make_uint4(pk2h(lS[0][0][0],lS[0][0][1]), pk2h(lS[1][0][0],lS[1][0][1]),
                       pk2h(lS[0][1][0],lS[0][1][1]), pk2h(lS[1][1][0],lS[1][1][1]));
        g_wSf[(size_t)idx * 2 + 1] = v;
    }
}

// ======================= fused block kernel =======================
// smem (dynamic, 84KB):
//   B1 [0,32K): 4 chunks [64t][64k] fp16 SW128 (activations, single-term)
//   G  [33792, 50176): [128 mid][64 t] fp16 SW128
//   accR [0, 33792) as [t][132] f32 (overlays dead B1 after phase 1)
//   accS [50176, 84992) as [m][68] f32
//   bias [84992, 86016)
#define SM_B1   0u
#define SM_G    33792u
#define SM_ACCR 0u
#define SM_ACCS 50176u
#define SM_BIAS 84992u
#define SMEM_SZ 86016

struct Frag { uint32_t a[4]; };
__device__ __forceinline__ Frag ldfrag(const uint4* p) {
    uint4 v = __ldg(p);
    Frag f; f.a[0] = v.x; f.a[1] = v.y; f.a[2] = v.z; f.a[3] = v.w;
    return f;
}

__global__ __launch_bounds__(256, 2)
void wn_hmma(const float* __restrict__ xin, float* __restrict__ xout,
             const uint4* __restrict__ Af, const uint4* __restrict__ Rf,
             const uint4* __restrict__ Sf,
             const float* __restrict__ brs, const float* __restrict__ bsk,
             float* __restrict__ skip_out,
             int d, int Tin, int Tout)
{
    extern __shared__ __align__(1024) char smem[];
    const uint32_t sbase = smem_to_u32(smem);
    const int tid  = threadIdx.x;
    const int wid  = tid >> 5;
    const int lane = tid & 31;
    const int t0   = blockIdx.x * TN;
    const int b    = blockIdx.y;
    // warp grid: 4 (m) x 2 (n); warp tile 32m x 32n
    const int mw  = wid >> 1;
    const int nw  = wid & 1;
    const int m0  = mw * 32;
    const int n0w = nw * 32;
    const int skip_base = Tout - SKIP_T;
    const bool need_skip = (t0 + TN > skip_base);

    const float* xbt = xin + (size_t)b * TMAX * C;   // [t][c]

    // ---------------- stage biases + B1 (coalesced row loads, single fp16) ----------------
    if (tid < 128) {
        ((float*)(smem + SM_BIAS))[tid]       = __ldg(brs + tid);
        ((float*)(smem + SM_BIAS + 512))[tid] = __ldg(bsk + tid);
    }
    {
        #pragma unroll
        for (int it = 0; it < 16; it++) {
            int job = wid * 16 + it;      // 0..127
            int tap = job >> 6, row = job & 63;
            int tabs = t0 + row + (tap ? d : 0);
            if (tabs >= Tin) tabs = Tin - 1;   // clamp: out-of-range columns discarded later
            float4 v = __ldg((const float4*)(xbt + (size_t)tabs * C) + lane);
            uint32_t o = (uint32_t)(tap * 2 + (lane >> 4)) * 8192u
                       + SWZ(row * 128 + (lane & 15) * 8);
            *(uint2*)(smem + SM_B1 + o) = make_uint2(pk2h(v.x, v.y), pk2h(v.z, v.w));
        }
    }
    __syncthreads();

    const int lrow = (((lane >> 4) & 1) << 3) + (lane & 7);
    const int lcol = (lane >> 3) & 1;

    // ---------------- phase 1: Y = W1 @ [x_tap0 ; x_tap1], K=256 (2-term weights) ----------------
    float acc1[2][4][4];
    #pragma unroll
    for (int mi = 0; mi < 2; mi++)
        #pragma unroll
        for (int j = 0; j < 4; j++)
            #pragma unroll
            for (int q = 0; q < 4; q++) acc1[mi][j][q] = 0.f;

    {
        Frag aH[2], aL[2];
        #pragma unroll
        for (int mi = 0; mi < 2; mi++) {
            const uint4* fp = Af + (((mw * 2 + mi) * 32 + lane) << 1);
            aH[mi] = ldfrag(fp); aL[mi] = ldfrag(fp + 1);
        }
        for (int ks = 0; ks < 16; ks++) {
            Frag nH[2], nL[2];
            if (ks < 15) {
                #pragma unroll
                for (int mi = 0; mi < 2; mi++) {
                    const uint4* np = Af + ((((ks + 1) * 8 + mw * 2 + mi) * 32 + lane) << 1);
                    nH[mi] = ldfrag(np); nL[mi] = ldfrag(np + 1);
                }
            }
            const int g = ks >> 2, kk = ks & 3;
            const uint32_t cb = sbase + SM_B1 + g * 8192;
            // hoisted: both jp's B fragments loaded before any MMA
            uint32_t bh0[4], bh1[4];
            {
                uint32_t off0 = ((n0w + lrow) << 7) + (kk << 5) + (lcol << 4);
                uint32_t off1 = ((n0w + 16 + lrow) << 7) + (kk << 5) + (lcol << 4);
                ldsm_x4(bh0, cb + SWZ(off0));
                ldsm_x4(bh1, cb + SWZ(off1));
            }
            #pragma unroll
            for (int mi = 0; mi < 2; mi++) {
                mma_f16(acc1[mi][0], aH[mi].a, bh0);
                mma_f16(acc1[mi][1], aH[mi].a, bh0 + 2);
                mma_f16(acc1[mi][0], aL[mi].a, bh0);
                mma_f16(acc1[mi][1], aL[mi].a, bh0 + 2);
                mma_f16(acc1[mi][2], aH[mi].a, bh1);
                mma_f16(acc1[mi][3], aH[mi].a, bh1 + 2);
                mma_f16(acc1[mi][2], aL[mi].a, bh1);
                mma_f16(acc1[mi][3], aL[mi].a, bh1 + 2);
            }
            aH[0] = nH[0]; aH[1] = nH[1]; aL[0] = nL[0]; aL[1] = nL[1];
        }
    }

    // ---------------- gate -> G smem [mid][t] single fp16 ----------------
    {
        const int r = lane >> 2, c2 = (lane & 3) * 2;
        #pragma unroll
        for (int mi = 0; mi < 2; mi++) {
            #pragma unroll
            for (int j = 0; j < 4; j++) {
                int m = m0 + mi * 16 + r;
                int n = n0w + j * 8 + c2;
                float g0 = gatef(acc1[mi][j][0]), g1 = gatef(acc1[mi][j][1]);
                float g2 = gatef(acc1[mi][j][2]), g3 = gatef(acc1[mi][j][3]);
                uint32_t oA = SWZ((uint32_t)m * 128u + n * 2);
                uint32_t oB = SWZ((uint32_t)(m + 8) * 128u + n * 2);
                *(uint32_t*)(smem + SM_G + oA) = pk2h(g0, g1);
                *(uint32_t*)(smem + SM_G + oB) = pk2h(g2, g3);
            }
        }
    }
    __syncthreads();   // G ready; B1 dead for everyone

    const int r_  = lane >> 2;
    const int c2_ = (lane & 3) * 2;
    float* xbo = xout + (size_t)b * TMAX * C;   // [t][c]
    // trans-ldmatrix per-lane address components
    const int trow = ((lane >> 3) & 1) * 8 + (lane & 7);
    const int tcol = (lane >> 4) * 8;

    // ---------------- merged phase 2: R (1-term) and S (1-term), frag-prefetched ----------------
    float accR[2][4][4], accS[2][4][4];
    #pragma unroll
    for (int mi = 0; mi < 2; mi++)
        #pragma unroll
        for (int j = 0; j < 4; j++)
            #pragma unroll
            for (int q = 0; q < 4; q++) { accR[mi][j][q] = 0.f; accS[mi][j][q] = 0.f; }

    {
        Frag rC[2], sC[2];
        #pragma unroll
        for (int mi = 0; mi < 2; mi++) {
            const int f0 = ((mw * 2 + mi) * 32 + lane) << 1;
            rC[mi] = ldfrag(Rf + f0);
            if (need_skip) sC[mi] = ldfrag(Sf + f0);
        }
        for (int ks = 0; ks < 8; ks++) {
            Frag rN[2], sN[2];
            if (ks < 7) {
                #pragma unroll
                for (int mi = 0; mi < 2; mi++) {
                    const int fn = (((ks + 1) * 8 + mw * 2 + mi) * 32 + lane) << 1;
                    rN[mi] = ldfrag(Rf + fn);
                    if (need_skip) sN[mi] = ldfrag(Sf + fn);
                }
            }
            const int kb = ks * 16;
            uint32_t bh0[4], bh1[4];
            {
                uint32_t off0 = SWZ((uint32_t)(kb + trow) * 128u + (n0w + tcol) * 2);
                uint32_t off1 = SWZ((uint32_t)(kb + trow) * 128u + (n0w + 16 + tcol) * 2);
                ldsm_x4_t(bh0, sbase + SM_G + off0);
                ldsm_x4_t(bh1, sbase + SM_G + off1);
            }
            #pragma unroll
            for (int mi = 0; mi < 2; mi++) {
                mma_f16(accR[mi][0], rC[mi].a, bh0);
                mma_f16(accR[mi][1], rC[mi].a, bh0 + 2);
                mma_f16(accR[mi][2], rC[mi].a, bh1);
                mma_f16(accR[mi][3], rC[mi].a, bh1 + 2);
                if (need_skip) {
                    mma_f16(accS[mi][0], sC[mi].a, bh0);
                    mma_f16(accS[mi][1], sC[mi].a, bh0 + 2);
                    mma_f16(accS[mi][2], sC[mi].a, bh1);
                    mma_f16(accS[mi][3], sC[mi].a, bh1 + 2);
                }
            }
            rC[0] = rN[0]; rC[1] = rN[1];
            if (need_skip) { sC[0] = sN[0]; sC[1] = sN[1]; }
        }
    }

    // ---------------- stash accR [t][132] (overlays dead B1) and accS [m][68] ----------------
    {
        float* st = (float*)(smem + SM_ACCR);
        #pragma unroll
        for (int mi = 0; mi < 2; mi++) {
            int m = m0 + mi * 16 + r_;
            #pragma unroll
            for (int j = 0; j < 4; j++) {
                int tl = n0w + j * 8 + c2_;
                st[tl * 132 + m]           = accR[mi][j][0];
                st[(tl + 1) * 132 + m]     = accR[mi][j][1];
                st[tl * 132 + m + 8]       = accR[mi][j][2];
                st[(tl + 1) * 132 + m + 8] = accR[mi][j][3];
            }
        }
    }
    if (need_skip) {
        float* st = (float*)(smem + SM_ACCS);
        #pragma unroll
        for (int mi = 0; mi < 2; mi++) {
            int m = m0 + mi * 16 + r_;
            #pragma unroll
            for (int j = 0; j < 4; j++) {
                int tl = n0w + j * 8 + c2_;
                st[m * 68 + tl]           = accS[mi][j][0];
                st[m * 68 + tl + 1]       = accS[mi][j][1];
                st[(m + 8) * 68 + tl]     = accS[mi][j][2];
                st[(m + 8) * 68 + tl + 1] = accS[mi][j][3];
            }
        }
    }
    __syncthreads();

    // ---------------- cooperative coalesced epilogue ----------------
    {
        const float* accRs = (const float*)(smem + SM_ACCR);
        const float* bvec = (const float*)(smem + SM_BIAS);
        #pragma unroll
        for (int iter = 0; iter < 2; iter++) {
            int row = iter * 32 + (tid >> 3);
            int col = (tid & 7) * 16;
            int tt = t0 + row;
            if (tt < Tout) {
                const float* src = accRs + row * 132 + col;
                const float* xr  = xbt + (size_t)(tt + d) * C + col;
                float* xo = xbo + (size_t)tt * C + col;
                #pragma unroll
                for (int j = 0; j < 4; j++) {
                    float4 a  = *(const float4*)(src + j * 4);
                    float4 rr = __ldg((const float4*)(xr + j * 4));
                    float4 bb = *(const float4*)(bvec + col + j * 4);
                    a.x += bb.x + rr.x; a.y += bb.y + rr.y;
                    a.z += bb.z + rr.z; a.w += bb.w + rr.w;
                    *(float4*)(xo + j * 4) = a;
                }
            }
        }
    }
    if (need_skip) {
        const float* accSs = (const float*)(smem + SM_ACCS);
        const float* bvec = (const float*)(smem + SM_BIAS + 512);
        const bool aligned = ((Tout & 3) == 0);
        const int l16 = tid & 15;
        #pragma unroll
        for (int i = 0; i < 8; i++) {
            int m = i * 16 + (tid >> 4);
            float bs = bvec[m];
            const float* src = accSs + m * 68 + l16 * 4;
            float* so = skip_out + ((size_t)b * C + m) * SKIP_T;
            int tt = t0 + l16 * 4;
            int ts = tt - skip_base;
            float4 v = *(const float4*)src;
            v.x += bs; v.y += bs; v.z += bs; v.w += bs;
            if (aligned && ts >= 0 && tt + 3 < Tout) {
                *(float4*)(so + ts) = v;
            } else {
                const float* vv = (const float*)&v;
                #pragma unroll
                for (int e = 0; e < 4; e++) {
                    int t2 = tt + e, ts2 = t2 - skip_base;
                    if (ts2 >= 0 && t2 < Tout) so[ts2] = vv[e];
                }
            }
        }
    }
}

// ======================= host =======================
static const int DIL[NB] = {
    1, 2, 4, 8, 16, 32, 64, 128, 256, 512,
    1, 2, 4, 8, 16, 32, 64, 128, 256, 512,
    1, 2, 4, 8, 16, 32, 64, 128, 256, 512,
    1, 2, 4, 8, 16, 32, 64, 128, 256, 512
};

extern "C" void kernel_launch(void* const* d_in, const int* in_sizes, int n_in,
                              void* d_out, int out_size)
{
    const float* x      = (const float*)d_in[0];
    const float* w_dil  = (const float*)d_in[1];
    const float* w_res  = (const float*)d_in[2];
    const float* b_res  = (const float*)d_in[3];
    const float* w_skip = (const float*)d_in[4];
    const float* b_skip = (const float*)d_in[5];
    float* out = (float*)d_out;

    float *xb0, *xb1;
    uint4 *wAf, *wRf, *wSf;
    cudaGetSymbolAddress((void**)&xb0, g_x0);
    cudaGetSymbolAddress((void**)&xb1, g_x1);
    cudaGetSymbolAddress((void**)&wAf, g_wAf);
    cudaGetSymbolAddress((void**)&wRf, g_wRf);
    cudaGetSymbolAddress((void**)&wSf, g_wSf);

    cudaFuncSetAttribute(wn_hmma, cudaFuncAttributeMaxDynamicSharedMemorySize, SMEM_SZ);

    {
        int total = NB * 16 * 8 * 32;
        prep_frags<<<(total + 255) / 256, 256>>>(w_dil, w_res, w_skip);
    }
    {
        dim3 g(TMAX / 32, C / 32, BATCH);
        transpose_in<<<g, dim3(32, 8)>>>(x, xb0);
    }

    int Tin = TMAX;
    const float* cur = xb0;
    for (int L = 0; L < NB; L++) {
        int dd   = DIL[L];
        int Tout = Tin - dd;
        float* xo = (L & 1) ? xb0 : xb1;
        dim3 grid((Tout + TN - 1) / TN, BATCH);
        wn_hmma<<<grid, 256, SMEM_SZ>>>(
            cur, xo,
            wAf + (size_t)L * 16 * 8 * 32 * 2,
            wRf + (size_t)L *  8 * 8 * 32 * 2,
            wSf + (size_t)L *  8 * 8 * 32 * 2,
            b_res + (size_t)L * C,
            b_skip + (size_t)L * C,
            out + (size_t)L * BATCH * C * SKIP_T,
            dd, Tin, Tout);
        cur = xo;
        Tin = Tout;
    }
}

// round 17
// speedup vs baseline: 1.1878x; 1.1878x over previous
#include <cuda_runtime.h>
#include <cuda_fp16.h>
#include <cstdint>

#define NB      40
#define C       128
#define BATCH   4
#define TMAX    8192
#define SKIP_T  4096
#define TN      64

// ======================= device scratch (no allocs allowed) =======================
__device__ float g_x0[BATCH * TMAX * C];
__device__ float g_x1[BATCH * TMAX * C];
// A-operand fragments (fp16), packed per-lane in mma register order. Each slot = 2 x uint4 (hi, lo).
__device__ uint4 g_wAf[NB * 16 * 8 * 32 * 2];   // GEMM1: 16 ksteps (hi used)
__device__ uint4 g_wRf[NB *  8 * 8 * 32 * 2];   // res:   8 ksteps (hi used)
__device__ uint4 g_wSf[NB *  8 * 8 * 32 * 2];   // skip:  8 ksteps (hi used)

#define SWZ(o) ((uint32_t)(o) ^ ((((uint32_t)(o)) >> 3) & 0x70u))

__device__ __forceinline__ uint32_t smem_to_u32(const void* p) {
    uint32_t a;
    asm("{ .reg .u64 t; cvta.to.shared.u64 t, %1; cvt.u32.u64 %0, t; }" : "=r"(a) : "l"(p));
    return a;
}

__device__ __forceinline__ void mma_f16(float* c, const uint32_t* a, const uint32_t* b) {
    asm volatile("mma.sync.aligned.m16n8k16.row.col.f32.f16.f16.f32 "
        "{%0,%1,%2,%3}, {%4,%5,%6,%7}, {%8,%9}, {%0,%1,%2,%3};"
        : "+f"(c[0]), "+f"(c[1]), "+f"(c[2]), "+f"(c[3])
        : "r"(a[0]), "r"(a[1]), "r"(a[2]), "r"(a[3]), "r"(b[0]), "r"(b[1]));
}

__device__ __forceinline__ void ldsm_x4(uint32_t* r, uint32_t addr) {
    asm volatile("ldmatrix.sync.aligned.m8n8.x4.shared.b16 {%0,%1,%2,%3}, [%4];"
        : "=r"(r[0]), "=r"(r[1]), "=r"(r[2]), "=r"(r[3]) : "r"(addr));
}
__device__ __forceinline__ void ldsm_x4_t(uint32_t* r, uint32_t addr) {
    asm volatile("ldmatrix.sync.aligned.m8n8.x4.trans.shared.b16 {%0,%1,%2,%3}, [%4];"
        : "=r"(r[0]), "=r"(r[1]), "=r"(r[2]), "=r"(r[3]) : "r"(addr));
}

__device__ __forceinline__ uint32_t pk2h(float a, float b) {
    __half2 t = __floats2half2_rn(a, b);
    return *reinterpret_cast<uint32_t*>(&t);
}
__device__ __forceinline__ void hilo_h(float v, float& h, float& l) {
    h = __half2float(__float2half_rn(v));
    l = v - h;
}

// gate(y) = tanh(y)*sigmoid(y) = (1-u)/(1+u^2), u = e^{-y}  (exact identity)
__device__ __forceinline__ float gatef(float y) {
    float u = __expf(-fmaxf(y, -15.f));
    return __fdividef(1.f - u, 1.f + u * u);
}

// ======================= transpose input [b][c][t] -> scratch [b][t][c] =======================
__global__ void transpose_in(const float* __restrict__ x, float* __restrict__ xt) {
    __shared__ float tile[32][33];
    const int b  = blockIdx.z;
    const int c0 = blockIdx.y * 32;
    const int tb = blockIdx.x * 32;
    const int tx = threadIdx.x, ty = threadIdx.y;
    #pragma unroll
    for (int i = 0; i < 32; i += 8)
        tile[ty + i][tx] = x[((size_t)b * C + c0 + ty + i) * TMAX + tb + tx];
    __syncthreads();
    #pragma unroll
    for (int i = 0; i < 32; i += 8)
        xt[((size_t)b * TMAX + tb + ty + i) * C + c0 + tx] = tile[tx][ty + i];
}

// ======================= prep: pack fp16 A fragments in register order =======================
__global__ void prep_frags(const float* __restrict__ w_dil,
                           const float* __restrict__ w_res,
                           const float* __restrict__ w_skip) {
    int idx = blockIdx.x * blockDim.x + threadIdx.x;
    if (idx < NB * 16 * 8 * 32) {
        int lane = idx & 31, mt = (idx >> 5) & 7, ks = (idx >> 8) & 15, blk = idx >> 12;
        int r = lane >> 2, c2 = (lane & 3) * 2;
        int mr[2] = { mt * 16 + r, mt * 16 + r + 8 };
        int kc[2] = { ks * 16 + c2, ks * 16 + c2 + 8 };
        float h[2][2][2], l[2][2][2];
        #pragma unroll
        for (int mi = 0; mi < 2; mi++)
            #pragma unroll
            for (int kh = 0; kh < 2; kh++)
                #pragma unroll
                for (int e = 0; e < 2; e++) {
                    int k = kc[kh] + e;
                    int tap = k >> 7, ch = k & 127;
                    float v = w_dil[(((size_t)blk * C + mr[mi]) * C + ch) * 2 + tap];
                    hilo_h(v, h[mi][kh][e], l[mi][kh][e]);
                }
        uint4 hv = { pk2h(h[0][0][0], h[0][0][1]), pk2h(h[1][0][0], h[1][0][1]),
                     pk2h(h[0][1][0], h[0][1][1]), pk2h(h[1][1][0], h[1][1][1]) };
        uint4 lv = { pk2h(l[0][0][0], l[0][0][1]), pk2h(l[1][0][0], l[1][0][1]),
                     pk2h(l[0][1][0], l[0][1][1]), pk2h(l[1][1][0], l[1][1][1]) };
        g_wAf[(size_t)idx * 2]     = hv;
        g_wAf[(size_t)idx * 2 + 1] = lv;
    }
    if (idx < NB * 8 * 8 * 32) {
        int lane = idx & 31, mt = (idx >> 5) & 7, ks = (idx >> 8) & 7, blk = idx >> 11;
        int r = lane >> 2, c2 = (lane & 3) * 2;
        int mr[2] = { mt * 16 + r, mt * 16 + r + 8 };
        int kc[2] = { ks * 16 + c2, ks * 16 + c2 + 8 };
        float hR[2][2][2], lR[2][2][2], hS[2][2][2], lS[2][2][2];
        #pragma unroll
        for (int mi = 0; mi < 2; mi++)
            #pragma unroll
            for (int kh = 0; kh < 2; kh++)
                #pragma unroll
                for (int e = 0; e < 2; e++) {
                    int k = kc[kh] + e;
                    float vr = w_res [((size_t)blk * C + mr[mi]) * C + k];
                    float vs = w_skip[((size_t)blk * C + mr[mi]) * C + k];
                    hilo_h(vr, hR[mi][kh][e], lR[mi][kh][e]);
                    hilo_h(vs, hS[mi][kh][e], lS[mi][kh][e]);
                }
        uint4 v;
        v = make_uint4(pk2h(hR[0][0][0],hR[0][0][1]), pk2h(hR[1][0][0],hR[1][0][1]),
                       pk2h(hR[0][1][0],hR[0][1][1]), pk2h(hR[1][1][0],hR[1][1][1]));
        g_wRf[(size_t)idx * 2] = v;
        v = make_uint4(pk2h(lR[0][0][0],lR[0][0][1]), pk2h(lR[1][0][0],lR[1][0][1]),
                       pk2h(lR[0][1][0],lR[0][1][1]), pk2h(lR[1][1][0],lR[1][1][1]));
        g_wRf[(size_t)idx * 2 + 1] = v;
        v = make_uint4(pk2h(hS[0][0][0],hS[0][0][1]), pk2h(hS[1][0][0],hS[1][0][1]),
                       pk2h(hS[0][1][0],hS[0][1][1]), pk2h(hS[1][1][0],hS[1][1][1]));
        g_wSf[(size_t)idx * 2] = v;
        v = make_uint4(pk2h(lS[0][0][0],lS[0][0][1]), pk2h(lS[1][0][0],lS[1][0][1]),
                       pk2h(lS[0][1][0],lS[0][1][1]), pk2h(lS[1][1][0],lS[1][1][1]));
        g_wSf[(size_t)idx * 2 + 1] = v;
    }
}

// ======================= fused block kernel =======================
// smem (dynamic, 84KB):
//   B1 [0,32K): 4 chunks [64t][64k] fp16 SW128 (activations, single-term)
//   G  [33792, 50176): [128 mid][64 t] fp16 SW128
//   accR [0, 33792) as [t][132] f32 (overlays dead B1 after phase 1)
//   accS [50176, 84992) as [m][68] f32
//   bias [84992, 86016)
#define SM_B1   0u
#define SM_G    33792u
#define SM_ACCR 0u
#define SM_ACCS 50176u
#define SM_BIAS 84992u
#define SMEM_SZ 86016

struct Frag { uint32_t a[4]; };
__device__ __forceinline__ Frag ldfrag(const uint4* p) {
    uint4 v = __ldg(p);
    Frag f; f.a[0] = v.x; f.a[1] = v.y; f.a[2] = v.z; f.a[3] = v.w;
    return f;
}

__global__ __launch_bounds__(256, 2)
void wn_hmma(const float* __restrict__ xin, float* __restrict__ xout,
             const uint4* __restrict__ Af, const uint4* __restrict__ Rf,
             const uint4* __restrict__ Sf,
             const float* __restrict__ brs, const float* __restrict__ bsk,
             float* __restrict__ skip_out,
             int d, int Tin, int Tout)
{
    extern __shared__ __align__(1024) char smem[];
    const uint32_t sbase = smem_to_u32(smem);
    const int tid  = threadIdx.x;
    const int wid  = tid >> 5;
    const int lane = tid & 31;
    const int t0   = blockIdx.x * TN;
    const int b    = blockIdx.y;
    // warp grid: 4 (m) x 2 (n); warp tile 32m x 32n
    const int mw  = wid >> 1;
    const int nw  = wid & 1;
    const int m0  = mw * 32;
    const int n0w = nw * 32;
    const int skip_base = Tout - SKIP_T;
    const bool need_skip = (t0 + TN > skip_base);

    const float* xbt = xin + (size_t)b * TMAX * C;   // [t][c]

    // ---------------- stage biases + B1 (coalesced row loads, single fp16) ----------------
    if (tid < 128) {
        ((float*)(smem + SM_BIAS))[tid]       = __ldg(brs + tid);
        ((float*)(smem + SM_BIAS + 512))[tid] = __ldg(bsk + tid);
    }
    {
        #pragma unroll
        for (int it = 0; it < 16; it++) {
            int job = wid * 16 + it;      // 0..127
            int tap = job >> 6, row = job & 63;
            int tabs = t0 + row + (tap ? d : 0);
            if (tabs >= Tin) tabs = Tin - 1;   // clamp: out-of-range columns discarded later
            float4 v = __ldg((const float4*)(xbt + (size_t)tabs * C) + lane);
            uint32_t o = (uint32_t)(tap * 2 + (lane >> 4)) * 8192u
                       + SWZ(row * 128 + (lane & 15) * 8);
            *(uint2*)(smem + SM_B1 + o) = make_uint2(pk2h(v.x, v.y), pk2h(v.z, v.w));
        }
    }
    __syncthreads();

    const int lrow = (((lane >> 4) & 1) << 3) + (lane & 7);
    const int lcol = (lane >> 3) & 1;

    // ---------------- phase 1: Y = W1 @ [x_tap0 ; x_tap1], K=256 (1-term weights) ----------------
    float acc1[2][4][4];
    #pragma unroll
    for (int mi = 0; mi < 2; mi++)
        #pragma unroll
        for (int j = 0; j < 4; j++)
            #pragma unroll
            for (int q = 0; q < 4; q++) acc1[mi][j][q] = 0.f;

    {
        Frag aH[2];
        #pragma unroll
        for (int mi = 0; mi < 2; mi++)
            aH[mi] = ldfrag(Af + (((mw * 2 + mi) * 32 + lane) << 1));
        for (int ks = 0; ks < 16; ks++) {
            Frag nH[2];
            if (ks < 15) {
                #pragma unroll
                for (int mi = 0; mi < 2; mi++)
                    nH[mi] = ldfrag(Af + ((((ks + 1) * 8 + mw * 2 + mi) * 32 + lane) << 1));
            }
            const int g = ks >> 2, kk = ks & 3;
            const uint32_t cb = sbase + SM_B1 + g * 8192;
            uint32_t bh0[4], bh1[4];
            {
                uint32_t off0 = ((n0w + lrow) << 7) + (kk << 5) + (lcol << 4);
                uint32_t off1 = ((n0w + 16 + lrow) << 7) + (kk << 5) + (lcol << 4);
                ldsm_x4(bh0, cb + SWZ(off0));
                ldsm_x4(bh1, cb + SWZ(off1));
            }
            #pragma unroll
            for (int mi = 0; mi < 2; mi++) {
                mma_f16(acc1[mi][0], aH[mi].a, bh0);
                mma_f16(acc1[mi][1], aH[mi].a, bh0 + 2);
                mma_f16(acc1[mi][2], aH[mi].a, bh1);
                mma_f16(acc1[mi][3], aH[mi].a, bh1 + 2);
            }
            aH[0] = nH[0]; aH[1] = nH[1];
        }
    }

    // ---------------- gate -> G smem [mid][t] single fp16 ----------------
    {
        const int r = lane >> 2, c2 = (lane & 3) * 2;
        #pragma unroll
        for (int mi = 0; mi < 2; mi++) {
            #pragma unroll
            for (int j = 0; j < 4; j++) {
                int m = m0 + mi * 16 + r;
                int n = n0w + j * 8 + c2;
                float g0 = gatef(acc1[mi][j][0]), g1 = gatef(acc1[mi][j][1]);
                float g2 = gatef(acc1[mi][j][2]), g3 = gatef(acc1[mi][j][3]);
                uint32_t oA = SWZ((uint32_t)m * 128u + n * 2);
                uint32_t oB = SWZ((uint32_t)(m + 8) * 128u + n * 2);
                *(uint32_t*)(smem + SM_G + oA) = pk2h(g0, g1);
                *(uint32_t*)(smem + SM_G + oB) = pk2h(g2, g3);
            }
        }
    }
    __syncthreads();   // G ready; B1 dead for everyone

    const int r_  = lane >> 2;
    const int c2_ = (lane & 3) * 2;
    float* xbo = xout + (size_t)b * TMAX * C;   // [t][c]
    // trans-ldmatrix per-lane address components
    const int trow = ((lane >> 3) & 1) * 8 + (lane & 7);
    const int tcol = (lane >> 4) * 8;

    // ---------------- merged phase 2: R (1-term) and S (1-term), inline frag loads ----------------
    float accR[2][4][4], accS[2][4][4];
    #pragma unroll
    for (int mi = 0; mi < 2; mi++)
        #pragma unroll
        for (int j = 0; j < 4; j++)
            #pragma unroll
            for (int q = 0; q < 4; q++) { accR[mi][j][q] = 0.f; accS[mi][j][q] = 0.f; }

    for (int ks = 0; ks < 8; ks++) {
        const int kb = ks * 16;
        uint32_t bh0[4], bh1[4];
        {
            uint32_t off0 = SWZ((uint32_t)(kb + trow) * 128u + (n0w + tcol) * 2);
            uint32_t off1 = SWZ((uint32_t)(kb + trow) * 128u + (n0w + 16 + tcol) * 2);
            ldsm_x4_t(bh0, sbase + SM_G + off0);
            ldsm_x4_t(bh1, sbase + SM_G + off1);
        }
        #pragma unroll
        for (int mi = 0; mi < 2; mi++) {
            const int fidx = ((ks * 8 + mw * 2 + mi) * 32 + lane) << 1;
            {
                Frag aH = ldfrag(Rf + fidx);
                mma_f16(accR[mi][0], aH.a, bh0);
                mma_f16(accR[mi][1], aH.a, bh0 + 2);
                mma_f16(accR[mi][2], aH.a, bh1);
                mma_f16(accR[mi][3], aH.a, bh1 + 2);
            }
            if (need_skip) {
                Frag aH = ldfrag(Sf + fidx);
                mma_f16(accS[mi][0], aH.a, bh0);
                mma_f16(accS[mi][1], aH.a, bh0 + 2);
                mma_f16(accS[mi][2], aH.a, bh1);
                mma_f16(accS[mi][3], aH.a, bh1 + 2);
            }
        }
    }

    // ---------------- stash accR [t][132] (overlays dead B1) and accS [m][68] ----------------
    {
        float* st = (float*)(smem + SM_ACCR);
        #pragma unroll
        for (int mi = 0; mi < 2; mi++) {
            int m = m0 + mi * 16 + r_;
            #pragma unroll
            for (int j = 0; j < 4; j++) {
                int tl = n0w + j * 8 + c2_;
                st[tl * 132 + m]           = accR[mi][j][0];
                st[(tl + 1) * 132 + m]     = accR[mi][j][1];
                st[tl * 132 + m + 8]       = accR[mi][j][2];
                st[(tl + 1) * 132 + m + 8] = accR[mi][j][3];
            }
        }
    }
    if (need_skip) {
        float* st = (float*)(smem + SM_ACCS);
        #pragma unroll
        for (int mi = 0; mi < 2; mi++) {
            int m = m0 + mi * 16 + r_;
            #pragma unroll
            for (int j = 0; j < 4; j++) {
                int tl = n0w + j * 8 + c2_;
                st[m * 68 + tl]           = accS[mi][j][0];
                st[m * 68 + tl + 1]       = accS[mi][j][1];
                st[(m + 8) * 68 + tl]     = accS[mi][j][2];
                st[(m + 8) * 68 + tl + 1] = accS[mi][j][3];
            }
        }
    }
    __syncthreads();

    // ---------------- cooperative coalesced epilogue ----------------
    {
        const float* accRs = (const float*)(smem + SM_ACCR);
        const float* bvec = (const float*)(smem + SM_BIAS);
        #pragma unroll
        for (int iter = 0; iter < 2; iter++) {
            int row = iter * 32 + (tid >> 3);
            int col = (tid & 7) * 16;
            int tt = t0 + row;
            if (tt < Tout) {
                const float* src = accRs + row * 132 + col;
                const float* xr  = xbt + (size_t)(tt + d) * C + col;
                float* xo = xbo + (size_t)tt * C + col;
                #pragma unroll
                for (int j = 0; j < 4; j++) {
                    float4 a  = *(const float4*)(src + j * 4);
                    float4 rr = __ldg((const float4*)(xr + j * 4));
                    float4 bb = *(const float4*)(bvec + col + j * 4);
                    a.x += bb.x + rr.x; a.y += bb.y + rr.y;
                    a.z += bb.z + rr.z; a.w += bb.w + rr.w;
                    *(float4*)(xo + j * 4) = a;
                }
            }
        }
    }
    if (need_skip) {
        const float* accSs = (const float*)(smem + SM_ACCS);
        const float* bvec = (const float*)(smem + SM_BIAS + 512);
        const bool aligned = ((Tout & 3) == 0);
        const int l16 = tid & 15;
        #pragma unroll
        for (int i = 0; i < 8; i++) {
            int m = i * 16 + (tid >> 4);
            float bs = bvec[m];
            const float* src = accSs + m * 68 + l16 * 4;
            float* so = skip_out + ((size_t)b * C + m) * SKIP_T;
            int tt = t0 + l16 * 4;
            int ts = tt - skip_base;
            float4 v = *(const float4*)src;
            v.x += bs; v.y += bs; v.z += bs; v.w += bs;
            if (aligned && ts >= 0 && tt + 3 < Tout) {
                *(float4*)(so + ts) = v;
            } else {
                const float* vv = (const float*)&v;
                #pragma unroll
                for (int e = 0; e < 4; e++) {
                    int t2 = tt + e, ts2 = t2 - skip_base;
                    if (ts2 >= 0 && t2 < Tout) so[ts2] = vv[e];
                }
            }
        }
    }
}

// ======================= host =======================
static const int DIL[NB] = {
    1, 2, 4, 8, 16, 32, 64, 128, 256, 512,
    1, 2, 4, 8, 16, 32, 64, 128, 256, 512,
    1, 2, 4, 8, 16, 32, 64, 128, 256, 512,
    1, 2, 4, 8, 16, 32, 64, 128, 256, 512
};

extern "C" void kernel_launch(void* const* d_in, const int* in_sizes, int n_in,
                              void* d_out, int out_size)
{
    const float* x      = (const float*)d_in[0];
    const float* w_dil  = (const float*)d_in[1];
    const float* w_res  = (const float*)d_in[2];
    const float* b_res  = (const float*)d_in[3];
    const float* w_skip = (const float*)d_in[4];
    const float* b_skip = (const float*)d_in[5];
    float* out = (float*)d_out;

    float *xb0, *xb1;
    uint4 *wAf, *wRf, *wSf;
    cudaGetSymbolAddress((void**)&xb0, g_x0);
    cudaGetSymbolAddress((void**)&xb1, g_x1);
    cudaGetSymbolAddress((void**)&wAf, g_wAf);
    cudaGetSymbolAddress((void**)&wRf, g_wRf);
    cudaGetSymbolAddress((void**)&wSf, g_wSf);

    cudaFuncSetAttribute(wn_hmma, cudaFuncAttributeMaxDynamicSharedMemorySize, SMEM_SZ);

    {
        int total = NB * 16 * 8 * 32;
        prep_frags<<<(total + 255) / 256, 256>>>(w_dil, w_res, w_skip);
    }
    {
        dim3 g(TMAX / 32, C / 32, BATCH);
        transpose_in<<<g, dim3(32, 8)>>>(x, xb0);
    }

    int Tin = TMAX;
    const float* cur = xb0;
    for (int L = 0; L < NB; L++) {
        int dd   = DIL[L];
        int Tout = Tin - dd;
        float* xo = (L & 1) ? xb0 : xb1;
        dim3 grid((Tout + TN - 1) / TN, BATCH);
        wn_hmma<<<grid, 256, SMEM_SZ>>>(
            cur, xo,
            wAf + (size_t)L * 16 * 8 * 32 * 2,
            wRf + (size_t)L *  8 * 8 * 32 * 2,
            wSf + (size_t)L *  8 * 8 * 32 * 2,
            b_res + (size_t)L * C,
            b_skip + (size_t)L * C,
            out + (size_t)L * BATCH * C * SKIP_T,
            dd, Tin, Tout);
        cur = xo;
        Tin = Tout;
    }
}